// round 3
// baseline (speedup 1.0000x reference)
#include <cuda_runtime.h>
#include <math.h>
#include <float.h>

#define DELTA     0.04f
#define LOG_CLAMP -100.0f
#define NT        256
#define B_MAX     8192

// Scratch: per-row partial losses (static device globals — allocation-free).
__device__ float g_row_ce[B_MAX];
__device__ float g_row_hu[B_MAX];

__device__ __forceinline__ float log1mp_term(float p) {
    // log1p(-p), clamped at LOG_CLAMP. For p < 1/64 use 4-term series
    // (abs err < 2e-10); rare large-p path uses accurate log1pf.
    float l;
    if (p < 0.015625f) {
        l = -p * (1.0f + p * (0.5f + p * (0.33333333333f + p * 0.25f)));
    } else {
        l = log1pf(-p);
    }
    return fmaxf(l, LOG_CLAMP);
}

__global__ __launch_bounds__(NT)
void row_kernel(const float* __restrict__ anchors,
                const float* __restrict__ offsets,
                const float* __restrict__ conf,
                const float* __restrict__ gt,
                int N)
{
    extern __shared__ float s_v[];           // N floats: conf, then exp(conf-max)
    __shared__ float s_wsum[NT / 32];
    __shared__ float s_wd[NT / 32];
    __shared__ int   s_wi[NT / 32];
    __shared__ float sh_cmax, sh_cidx, sh_lse, sh_inv;
    __shared__ int   sh_bi;

    const int tid  = threadIdx.x;
    const int lane = tid & 31;
    const int wid  = tid >> 5;
    const int b    = blockIdx.x;

    const float* crow = conf    + (size_t)b * N;
    const float* arow = anchors + (size_t)b * 2 * N;
    const float gx = gt[2 * b];
    const float gy = gt[2 * b + 1];

    const bool vec_ok = ((N & 3) == 0);

    // ---------- Pass 1: conf -> smem (+max);  anchors -> (d^2, idx) argmin ----------
    float cmax = -FLT_MAX;
    float bd = FLT_MAX;
    int   bi = 0x7fffffff;

    if (vec_ok) {
        const int n4 = N >> 2;
        const float4* c4 = (const float4*)crow;
        float4* s4 = (float4*)s_v;
        for (int i = tid; i < n4; i += NT) {
            float4 v = c4[i];
            s4[i] = v;
            cmax = fmaxf(cmax, fmaxf(fmaxf(v.x, v.y), fmaxf(v.z, v.w)));
        }
        const int m4 = N >> 1;                 // float4 = 2 (x,y) points
        const float4* a4 = (const float4*)arow;
        for (int i = tid; i < m4; i += NT) {
            float4 v = a4[i];
            float dx = v.x - gx, dy = v.y - gy;
            float d0 = dx * dx + dy * dy;
            dx = v.z - gx; dy = v.w - gy;
            float d1 = dx * dx + dy * dy;
            int i0 = 2 * i;
            if (d0 < bd || (d0 == bd && i0 < bi))       { bd = d0; bi = i0; }
            if (d1 < bd || (d1 == bd && (i0 + 1) < bi)) { bd = d1; bi = i0 + 1; }
        }
    } else {
        for (int i = tid; i < N; i += NT) {
            float v = crow[i];
            s_v[i] = v;
            cmax = fmaxf(cmax, v);
        }
        for (int i = tid; i < N; i += NT) {
            float dx = arow[2 * i] - gx, dy = arow[2 * i + 1] - gy;
            float d = dx * dx + dy * dy;
            if (d < bd || (d == bd && i < bi)) { bd = d; bi = i; }
        }
    }

    // warp-level reduce (max + lexicographic argmin pair)
    #pragma unroll
    for (int o = 16; o > 0; o >>= 1) {
        cmax = fmaxf(cmax, __shfl_down_sync(0xffffffffu, cmax, o));
        float od = __shfl_down_sync(0xffffffffu, bd, o);
        int   oi = __shfl_down_sync(0xffffffffu, bi, o);
        if (od < bd || (od == bd && oi < bi)) { bd = od; bi = oi; }
    }
    if (lane == 0) { s_wsum[wid] = cmax; s_wd[wid] = bd; s_wi[wid] = bi; }
    __syncthreads();
    if (wid == 0) {
        const int NW = NT / 32;
        cmax = (lane < NW) ? s_wsum[lane] : -FLT_MAX;
        bd   = (lane < NW) ? s_wd[lane]   : FLT_MAX;
        bi   = (lane < NW) ? s_wi[lane]   : 0x7fffffff;
        #pragma unroll
        for (int o = 16; o > 0; o >>= 1) {
            cmax = fmaxf(cmax, __shfl_down_sync(0xffffffffu, cmax, o));
            float od = __shfl_down_sync(0xffffffffu, bd, o);
            int   oi = __shfl_down_sync(0xffffffffu, bi, o);
            if (od < bd || (od == bd && oi < bi)) { bd = od; bi = oi; }
        }
        if (lane == 0) { sh_cmax = cmax; sh_bi = bi; }
    }
    __syncthreads();
    if (tid == 0) sh_cidx = s_v[sh_bi];      // save conf[idx] before exp overwrite
    __syncthreads();

    // ---------- Pass 2: exp in place, sum -> lse ----------
    cmax = sh_cmax;
    float lsum = 0.0f;
    if (vec_ok) {
        const int n4 = N >> 2;
        float4* s4 = (float4*)s_v;
        for (int i = tid; i < n4; i += NT) {
            float4 v = s4[i];
            v.x = __expf(v.x - cmax);
            v.y = __expf(v.y - cmax);
            v.z = __expf(v.z - cmax);
            v.w = __expf(v.w - cmax);
            s4[i] = v;
            lsum += (v.x + v.y) + (v.z + v.w);
        }
    } else {
        for (int i = tid; i < N; i += NT) {
            float e = __expf(s_v[i] - cmax);
            s_v[i] = e;
            lsum += e;
        }
    }
    #pragma unroll
    for (int o = 16; o > 0; o >>= 1)
        lsum += __shfl_down_sync(0xffffffffu, lsum, o);
    if (lane == 0) s_wsum[wid] = lsum;
    __syncthreads();
    if (tid == 0) {
        float s = 0.0f;
        #pragma unroll
        for (int w = 0; w < NT / 32; w++) s += s_wsum[w];
        sh_lse = cmax + logf(s);
        sh_inv = 1.0f / s;
    }
    __syncthreads();

    // ---------- Pass 3: sum of clamped log1p(-p) ----------
    const float inv = sh_inv;
    float S = 0.0f;
    if (vec_ok) {
        const int n4 = N >> 2;
        const float4* s4 = (const float4*)s_v;
        for (int i = tid; i < n4; i += NT) {
            float4 e = s4[i];
            S += log1mp_term(e.x * inv);
            S += log1mp_term(e.y * inv);
            S += log1mp_term(e.z * inv);
            S += log1mp_term(e.w * inv);
        }
    } else {
        for (int i = tid; i < N; i += NT)
            S += log1mp_term(s_v[i] * inv);
    }
    #pragma unroll
    for (int o = 16; o > 0; o >>= 1)
        S += __shfl_down_sync(0xffffffffu, S, o);
    if (lane == 0) s_wsum[wid] = S;
    __syncthreads();

    if (tid == 0) {
        float Ssum = 0.0f;
        #pragma unroll
        for (int w = 0; w < NT / 32; w++) Ssum += s_wsum[w];

        const int   idx   = sh_bi;
        const float e_idx = s_v[idx];               // exp(c_idx - cmax)
        const float p_idx = e_idx * inv;
        const float l_idx = log1mp_term(p_idx);     // same formula as in Ssum
        const float logp  = fmaxf(sh_cidx - sh_lse, LOG_CLAMP);
        const float ce    = -(logp + (Ssum - l_idx));

        const float ax = arow[2 * idx];
        const float ay = arow[2 * idx + 1];
        const float* orow = offsets + (size_t)b * 2 * N;
        const float ox = orow[2 * idx];
        const float oy = orow[2 * idx + 1];
        const float x0 = ox - (gx - ax);
        const float x1 = oy - (gy - ay);
        float h = 0.0f;
        float a0 = fabsf(x0);
        h += (a0 <= DELTA) ? 0.5f * x0 * x0 : DELTA * (a0 - 0.5f * DELTA);
        float a1 = fabsf(x1);
        h += (a1 <= DELTA) ? 0.5f * x1 * x1 : DELTA * (a1 - 0.5f * DELTA);

        g_row_ce[b] = ce;
        g_row_hu[b] = h;
    }
}

// Deterministic fixed-tree final reduction over B rows.
__global__ __launch_bounds__(256)
void reduce_kernel(float* __restrict__ out, int B, int out_size)
{
    __shared__ float sc[256];
    __shared__ float sh[256];
    const int tid = threadIdx.x;
    float c = 0.0f, h = 0.0f;
    for (int i = tid; i < B; i += 256) {
        c += g_row_ce[i];
        h += g_row_hu[i];
    }
    sc[tid] = c; sh[tid] = h;
    __syncthreads();
    #pragma unroll
    for (int s = 128; s > 0; s >>= 1) {
        if (tid < s) { sc[tid] += sc[tid + s]; sh[tid] += sh[tid + s]; }
        __syncthreads();
    }
    if (tid == 0) {
        float ce = sc[0], hu = sh[0];
        out[0] = ce + hu;                 // total_loss
        if (out_size > 1) out[1] = ce;    // ce_loss
        if (out_size > 2) out[2] = hu;    // huber_loss
    }
}

extern "C" void kernel_launch(void* const* d_in, const int* in_sizes, int n_in,
                              void* d_out, int out_size)
{
    const float* anchors = (const float*)d_in[0];   // (B, N, 2)
    const float* offsets = (const float*)d_in[1];   // (B, N, 2)
    const float* conf    = (const float*)d_in[2];   // (B, N)
    const float* gt      = (const float*)d_in[3];   // (B, 2)

    const int BN = in_sizes[2];
    const int B  = in_sizes[3] / 2;
    const int N  = BN / B;

    const size_t smem = (size_t)N * sizeof(float);
    row_kernel<<<B, NT, smem>>>(anchors, offsets, conf, gt, N);
    reduce_kernel<<<1, 256>>>((float*)d_out, B, out_size);
}

// round 4
// speedup vs baseline: 1.3982x; 1.3982x over previous
#include <cuda_runtime.h>
#include <math.h>
#include <float.h>

#define DELTA     0.04f
#define LOG_CLAMP -100.0f
#define NT        256
#define NW        (NT / 32)
#define B_MAX     8192

// Scratch (allocation-free): per-row partial losses + completion ticket.
__device__ float g_row_ce[B_MAX];
__device__ float g_row_hu[B_MAX];
__device__ int   g_count;          // zero-initialized at module load; reset by last CTA

__device__ __forceinline__ float log1mp_term(float p) {
    // log1p(-p), clamped at LOG_CLAMP. For p < 1/64 the 4-term series
    // (abs err < p^5/5 < 2e-10); rare large-p path uses accurate log1pf.
    float l;
    if (p < 0.015625f) {
        l = -p * (1.0f + p * (0.5f + p * (0.33333333333f + p * 0.25f)));
    } else {
        l = log1pf(-p);
    }
    return fmaxf(l, LOG_CLAMP);
}

// ======================= FAST PATH: N == 2048 ==============================
// Per thread: 2 conf float4 + 4 anchor float4, all loads front-batched
// (MLP_p1 = 6). No dynamic smem. Softmax-log1mp folded into power sums.
__global__ __launch_bounds__(NT)
void row_kernel_2048(const float* __restrict__ anchors,
                     const float* __restrict__ offsets,
                     const float* __restrict__ conf,
                     const float* __restrict__ gt,
                     float* __restrict__ out, int out_size, int B)
{
    constexpr int N = 2048;
    __shared__ float s_f[4][NW];
    __shared__ int   s_i[NW];
    __shared__ float sh_cmax, sh_s, sh_inv;
    __shared__ int   sh_islast;

    const int tid  = threadIdx.x;
    const int lane = tid & 31;
    const int wid  = tid >> 5;
    const int b    = blockIdx.x;

    const float* crow = conf    + (size_t)b * N;
    const float* arow = anchors + (size_t)b * 2 * N;
    const float* orow = offsets + (size_t)b * 2 * N;
    const float gx = gt[2 * b];
    const float gy = gt[2 * b + 1];

    const float4* c4 = (const float4*)crow;
    const float4* a4 = (const float4*)arow;

    // ---- batched loads: 6 independent float4 LDGs per thread ----
    float4 c0 = c4[tid];
    float4 c1 = c4[tid + NT];
    float4 a0 = a4[tid];
    float4 a1 = a4[tid + NT];
    float4 a2 = a4[tid + 2 * NT];
    float4 a3 = a4[tid + 3 * NT];

    float cmax = fmaxf(fmaxf(fmaxf(c0.x, c0.y), fmaxf(c0.z, c0.w)),
                       fmaxf(fmaxf(c1.x, c1.y), fmaxf(c1.z, c1.w)));

    float bd = FLT_MAX;
    int   bi = 0x7fffffff;
    {
        float dx, dy, d;
#define PROC2(v, base)                                                        \
        dx = (v).x - gx; dy = (v).y - gy; d = dx * dx + dy * dy;              \
        if (d < bd || (d == bd && (base) < bi))       { bd = d; bi = (base); }\
        dx = (v).z - gx; dy = (v).w - gy; d = dx * dx + dy * dy;              \
        if (d < bd || (d == bd && (base) + 1 < bi))   { bd = d; bi = (base) + 1; }
        PROC2(a0, 2 * tid)
        PROC2(a1, 2 * (tid + NT))
        PROC2(a2, 2 * (tid + 2 * NT))
        PROC2(a3, 2 * (tid + 3 * NT))
#undef PROC2
    }

    // ---- stage A: block reduce (max, lexicographic argmin) ----
    #pragma unroll
    for (int o = 16; o > 0; o >>= 1) {
        cmax = fmaxf(cmax, __shfl_down_sync(0xffffffffu, cmax, o));
        float od = __shfl_down_sync(0xffffffffu, bd, o);
        int   oi = __shfl_down_sync(0xffffffffu, bi, o);
        if (od < bd || (od == bd && oi < bi)) { bd = od; bi = oi; }
    }
    if (lane == 0) { s_f[0][wid] = cmax; s_f[1][wid] = bd; s_i[wid] = bi; }
    __syncthreads();
    if (wid == 0) {
        cmax = (lane < NW) ? s_f[0][lane] : -FLT_MAX;
        bd   = (lane < NW) ? s_f[1][lane] : FLT_MAX;
        bi   = (lane < NW) ? s_i[lane]    : 0x7fffffff;
        #pragma unroll
        for (int o = 16; o > 0; o >>= 1) {
            cmax = fmaxf(cmax, __shfl_down_sync(0xffffffffu, cmax, o));
            float od = __shfl_down_sync(0xffffffffu, bd, o);
            int   oi = __shfl_down_sync(0xffffffffu, bi, o);
            if (od < bd || (od == bd && oi < bi)) { bd = od; bi = oi; }
        }
        if (lane == 0) sh_cmax = cmax;
    }

    // tid0 prefetches the idx gather (L2 hits — the row was just streamed).
    float cidx = 0.f, axv = 0.f, ayv = 0.f, oxv = 0.f, oyv = 0.f;
    int   idx  = 0;
    if (tid == 0) {
        idx  = bi;                      // final argmin lives in tid0's register
        cidx = crow[idx];
        axv  = arow[2 * idx];
        ayv  = arow[2 * idx + 1];
        oxv  = orow[2 * idx];
        oyv  = orow[2 * idx + 1];
    }
    __syncthreads();

    // ---- stage B: exp from registers; accumulate power sums s1..s4 ----
    const float m = sh_cmax;
    float e[8];
    e[0] = __expf(c0.x - m); e[1] = __expf(c0.y - m);
    e[2] = __expf(c0.z - m); e[3] = __expf(c0.w - m);
    e[4] = __expf(c1.x - m); e[5] = __expf(c1.y - m);
    e[6] = __expf(c1.z - m); e[7] = __expf(c1.w - m);

    float s1 = 0.f, s2 = 0.f, s3 = 0.f, s4 = 0.f;
    #pragma unroll
    for (int k = 0; k < 8; k++) {
        float ek = e[k];
        float t2 = ek * ek;
        s1 += ek;
        s2 += t2;
        s3 += t2 * ek;
        s4 += t2 * t2;
    }
    #pragma unroll
    for (int o = 16; o > 0; o >>= 1) {
        s1 += __shfl_down_sync(0xffffffffu, s1, o);
        s2 += __shfl_down_sync(0xffffffffu, s2, o);
        s3 += __shfl_down_sync(0xffffffffu, s3, o);
        s4 += __shfl_down_sync(0xffffffffu, s4, o);
    }
    if (lane == 0) {
        s_f[0][wid] = s1; s_f[1][wid] = s2; s_f[2][wid] = s3; s_f[3][wid] = s4;
    }
    __syncthreads();

    float m2acc = 0.f, m3acc = 0.f, m4acc = 0.f;   // tid0-held
    if (tid == 0) {
        float t1 = 0.f, t2 = 0.f, t3 = 0.f, t4 = 0.f;
        #pragma unroll
        for (int w = 0; w < NW; w++) {
            t1 += s_f[0][w]; t2 += s_f[1][w]; t3 += s_f[2][w]; t4 += s_f[3][w];
        }
        sh_s   = t1;
        sh_inv = 1.0f / t1;
        m2acc = t2; m3acc = t3; m4acc = t4;
    }
    __syncthreads();

    // ---- rare exact fallback: only if s < 64 (then some p may be >= 1/64) ----
    const float s_total = sh_s;           // block-uniform -> barriers below safe
    float Sx = 0.f;
    if (s_total < 64.0f) {
        const float inv = sh_inv;
        float S = 0.f;
        #pragma unroll
        for (int k = 0; k < 8; k++) S += log1mp_term(e[k] * inv);
        #pragma unroll
        for (int o = 16; o > 0; o >>= 1)
            S += __shfl_down_sync(0xffffffffu, S, o);
        if (lane == 0) s_f[0][wid] = S;
        __syncthreads();
        if (tid == 0) {
            float t = 0.f;
            #pragma unroll
            for (int w = 0; w < NW; w++) t += s_f[0][w];
            Sx = t;
        }
        __syncthreads();
    }

    // ---- epilogue: per-row ce + huber (tid0) ----
    if (tid == 0) {
        const float s   = s_total;
        const float inv = sh_inv;
        const float lse = cmax + logf(s);          // tid0 still holds final cmax

        float Ssum;
        if (s < 64.0f) {
            Ssum = Sx;
        } else {
            // sum_i log1p(-p_i) = -(sum p + M2/2 + M3/3 + M4/4), sum p == 1
            const float inv2 = inv * inv;
            const float M2 = m2acc * inv2;
            const float M3 = m3acc * inv2 * inv;
            const float M4 = m4acc * inv2 * inv2;
            Ssum = -(1.0f + 0.5f * M2 + 0.33333333333f * M3 + 0.25f * M4);
        }

        const float e_idx = __expf(cidx - cmax);
        const float p_idx = e_idx * inv;
        const float l_idx = log1mp_term(p_idx);
        const float logp  = fmaxf(cidx - lse, LOG_CLAMP);
        const float ce    = -(logp + (Ssum - l_idx));

        const float x0 = oxv - (gx - axv);
        const float x1 = oyv - (gy - ayv);
        float h = 0.0f;
        float aa0 = fabsf(x0);
        h += (aa0 <= DELTA) ? 0.5f * x0 * x0 : DELTA * (aa0 - 0.5f * DELTA);
        float aa1 = fabsf(x1);
        h += (aa1 <= DELTA) ? 0.5f * x1 * x1 : DELTA * (aa1 - 0.5f * DELTA);

        g_row_ce[b] = ce;
        g_row_hu[b] = h;

        __threadfence();
        int t = atomicAdd(&g_count, 1);
        sh_islast = (t == gridDim.x - 1) ? 1 : 0;
    }
    __syncthreads();

    // ---- fused deterministic final reduction (last CTA only) ----
    if (sh_islast) {
        __threadfence();                 // acquire: see all rows' writes
        float c = 0.f, h = 0.f;
        for (int i = tid; i < B; i += NT) {
            c += g_row_ce[i];
            h += g_row_hu[i];
        }
        #pragma unroll
        for (int o = 16; o > 0; o >>= 1) {
            c += __shfl_down_sync(0xffffffffu, c, o);
            h += __shfl_down_sync(0xffffffffu, h, o);
        }
        if (lane == 0) { s_f[0][wid] = c; s_f[1][wid] = h; }
        __syncthreads();
        if (tid == 0) {
            float ce = 0.f, hu = 0.f;
            #pragma unroll
            for (int w = 0; w < NW; w++) { ce += s_f[0][w]; hu += s_f[1][w]; }
            out[0] = ce + hu;
            if (out_size > 1) out[1] = ce;
            if (out_size > 2) out[2] = hu;
            g_count = 0;                 // self-reset for graph replay
        }
    }
}

// ======================= GENERIC FALLBACK (N != 2048) ======================
__global__ __launch_bounds__(NT)
void row_kernel(const float* __restrict__ anchors,
                const float* __restrict__ offsets,
                const float* __restrict__ conf,
                const float* __restrict__ gt,
                int N)
{
    extern __shared__ float s_v[];
    __shared__ float s_wsum[NW];
    __shared__ float s_wd[NW];
    __shared__ int   s_wi[NW];
    __shared__ float sh_cmax, sh_cidx, sh_lse, sh_inv;
    __shared__ int   sh_bi;

    const int tid  = threadIdx.x;
    const int lane = tid & 31;
    const int wid  = tid >> 5;
    const int b    = blockIdx.x;

    const float* crow = conf    + (size_t)b * N;
    const float* arow = anchors + (size_t)b * 2 * N;
    const float gx = gt[2 * b];
    const float gy = gt[2 * b + 1];

    float cmax = -FLT_MAX;
    float bd = FLT_MAX;
    int   bi = 0x7fffffff;

    for (int i = tid; i < N; i += NT) {
        float v = crow[i];
        s_v[i] = v;
        cmax = fmaxf(cmax, v);
    }
    for (int i = tid; i < N; i += NT) {
        float dx = arow[2 * i] - gx, dy = arow[2 * i + 1] - gy;
        float d = dx * dx + dy * dy;
        if (d < bd || (d == bd && i < bi)) { bd = d; bi = i; }
    }

    #pragma unroll
    for (int o = 16; o > 0; o >>= 1) {
        cmax = fmaxf(cmax, __shfl_down_sync(0xffffffffu, cmax, o));
        float od = __shfl_down_sync(0xffffffffu, bd, o);
        int   oi = __shfl_down_sync(0xffffffffu, bi, o);
        if (od < bd || (od == bd && oi < bi)) { bd = od; bi = oi; }
    }
    if (lane == 0) { s_wsum[wid] = cmax; s_wd[wid] = bd; s_wi[wid] = bi; }
    __syncthreads();
    if (wid == 0) {
        cmax = (lane < NW) ? s_wsum[lane] : -FLT_MAX;
        bd   = (lane < NW) ? s_wd[lane]   : FLT_MAX;
        bi   = (lane < NW) ? s_wi[lane]   : 0x7fffffff;
        #pragma unroll
        for (int o = 16; o > 0; o >>= 1) {
            cmax = fmaxf(cmax, __shfl_down_sync(0xffffffffu, cmax, o));
            float od = __shfl_down_sync(0xffffffffu, bd, o);
            int   oi = __shfl_down_sync(0xffffffffu, bi, o);
            if (od < bd || (od == bd && oi < bi)) { bd = od; bi = oi; }
        }
        if (lane == 0) { sh_cmax = cmax; sh_bi = bi; }
    }
    __syncthreads();
    if (tid == 0) sh_cidx = s_v[sh_bi];
    __syncthreads();

    cmax = sh_cmax;
    float lsum = 0.0f;
    for (int i = tid; i < N; i += NT) {
        float ev = __expf(s_v[i] - cmax);
        s_v[i] = ev;
        lsum += ev;
    }
    #pragma unroll
    for (int o = 16; o > 0; o >>= 1)
        lsum += __shfl_down_sync(0xffffffffu, lsum, o);
    if (lane == 0) s_wsum[wid] = lsum;
    __syncthreads();
    if (tid == 0) {
        float s = 0.0f;
        #pragma unroll
        for (int w = 0; w < NW; w++) s += s_wsum[w];
        sh_lse = cmax + logf(s);
        sh_inv = 1.0f / s;
    }
    __syncthreads();

    const float inv = sh_inv;
    float S = 0.0f;
    for (int i = tid; i < N; i += NT)
        S += log1mp_term(s_v[i] * inv);
    #pragma unroll
    for (int o = 16; o > 0; o >>= 1)
        S += __shfl_down_sync(0xffffffffu, S, o);
    if (lane == 0) s_wsum[wid] = S;
    __syncthreads();

    if (tid == 0) {
        float Ssum = 0.0f;
        #pragma unroll
        for (int w = 0; w < NW; w++) Ssum += s_wsum[w];

        const int   idx   = sh_bi;
        const float e_idx = s_v[idx];
        const float p_idx = e_idx * inv;
        const float l_idx = log1mp_term(p_idx);
        const float logp  = fmaxf(sh_cidx - sh_lse, LOG_CLAMP);
        const float ce    = -(logp + (Ssum - l_idx));

        const float ax = arow[2 * idx];
        const float ay = arow[2 * idx + 1];
        const float* orow = offsets + (size_t)b * 2 * N;
        const float ox = orow[2 * idx];
        const float oy = orow[2 * idx + 1];
        const float x0 = ox - (gx - ax);
        const float x1 = oy - (gy - ay);
        float h = 0.0f;
        float a0 = fabsf(x0);
        h += (a0 <= DELTA) ? 0.5f * x0 * x0 : DELTA * (a0 - 0.5f * DELTA);
        float a1 = fabsf(x1);
        h += (a1 <= DELTA) ? 0.5f * x1 * x1 : DELTA * (a1 - 0.5f * DELTA);

        g_row_ce[b] = ce;
        g_row_hu[b] = h;
    }
}

__global__ __launch_bounds__(256)
void reduce_kernel(float* __restrict__ out, int B, int out_size)
{
    __shared__ float sc[256];
    __shared__ float sh[256];
    const int tid = threadIdx.x;
    float c = 0.0f, h = 0.0f;
    for (int i = tid; i < B; i += 256) {
        c += g_row_ce[i];
        h += g_row_hu[i];
    }
    sc[tid] = c; sh[tid] = h;
    __syncthreads();
    #pragma unroll
    for (int s = 128; s > 0; s >>= 1) {
        if (tid < s) { sc[tid] += sc[tid + s]; sh[tid] += sh[tid + s]; }
        __syncthreads();
    }
    if (tid == 0) {
        float ce = sc[0], hu = sh[0];
        out[0] = ce + hu;
        if (out_size > 1) out[1] = ce;
        if (out_size > 2) out[2] = hu;
    }
}

extern "C" void kernel_launch(void* const* d_in, const int* in_sizes, int n_in,
                              void* d_out, int out_size)
{
    const float* anchors = (const float*)d_in[0];   // (B, N, 2)
    const float* offsets = (const float*)d_in[1];   // (B, N, 2)
    const float* conf    = (const float*)d_in[2];   // (B, N)
    const float* gt      = (const float*)d_in[3];   // (B, 2)

    const int BN = in_sizes[2];
    const int B  = in_sizes[3] / 2;
    const int N  = BN / B;

    if (N == 2048 && B <= B_MAX) {
        row_kernel_2048<<<B, NT>>>(anchors, offsets, conf, gt,
                                   (float*)d_out, out_size, B);
    } else {
        const size_t smem = (size_t)N * sizeof(float);
        row_kernel<<<B, NT, smem>>>(anchors, offsets, conf, gt, N);
        reduce_kernel<<<1, 256>>>((float*)d_out, B, out_size);
    }
}